// round 15
// baseline (speedup 1.0000x reference)
#include <cuda_runtime.h>
#include <cstdint>

// DenseWarpLayer: bilinear warp, N=8, H=512, W=512, C=32 fp32.
// R15: tests the LAST untried lever — write-stream burstiness. R6's 32x8
// tile walk (gathers unchanged), but each tile-row's output (32 px * 128B =
// 4KB contiguous) is staged in a double-buffered smem row and written with
// ONE cp.async.bulk (TMA-path, async proxy) store instead of 256 fine-grain
// STG.128s interleaved with gather reads. If the ~69%-of-spec plateau is
// read/write turnaround at the HBM controller, coarse 4KB write bursts
// should raise efficiency; if flat, the ceiling is pattern-independent and
// R10 (92.2us) stands as final.

#define N_ 8
#define H_ 512
#define W_ 512
#define C4_ 8u            // 32 channels = 8 float4
#define ROW4 (W_ * C4_)   // float4 per image row = 4096
#define TILE_W 32u
#define TILE_H 8u
#define TILES_X 16u
#define TILES_PER_IMG 1024u
#define ROW_BYTES 4096u   // 32 px * 32 ch * 4B

__device__ __forceinline__ float4 bilerp4(const float4 tl, const float4 tr,
                                          const float4 bl, const float4 br,
                                          const float ax, const float ay)
{
    float4 r; float top, bot;
    top = tl.x + ax * (tr.x - tl.x); bot = bl.x + ax * (br.x - bl.x);
    r.x = top + ay * (bot - top);
    top = tl.y + ax * (tr.y - tl.y); bot = bl.y + ax * (br.y - bl.y);
    r.y = top + ay * (bot - top);
    top = tl.z + ax * (tr.z - tl.z); bot = bl.z + ax * (br.z - bl.z);
    r.z = top + ay * (bot - top);
    top = tl.w + ax * (tr.w - tl.w); bot = bl.w + ax * (br.w - bl.w);
    r.w = top + ay * (bot - top);
    return r;
}

__global__ __launch_bounds__(256, 8)
void dense_warp_kernel(const float* __restrict__ image,
                       const float* __restrict__ flow,
                       float* __restrict__ out)
{
    // double-buffered output staging: [stage][tid] = this thread's float4
    __shared__ __align__(16) float4 obuf[2][256];

    const unsigned tid = threadIdx.x;
    const unsigned c4  = tid & 7u;        // channel quad
    const unsigned col = tid >> 3;        // column within tile, 0..31

    const unsigned blk = blockIdx.x;
    const unsigned n   = blk >> 10;                  // / TILES_PER_IMG
    const unsigned rem = blk & (TILES_PER_IMG - 1u);
    const unsigned ty  = rem >> 4;                   // / TILES_X
    const unsigned tx  = rem & (TILES_X - 1u);

    const unsigned x    = tx * TILE_W + col;
    const unsigned y0   = ty * TILE_H;
    const unsigned nH   = n * H_;
    const unsigned rowPix0 = (nH + y0) * W_ + tx * TILE_W; // first pixel of row 0

    const float2* fl2  = reinterpret_cast<const float2*>(flow);
    const float4* img4 = reinterpret_cast<const float4*>(image);

    // smem staging address: tid's slot must be laid out so that the 4KB
    // buffer is EXACTLY the output row: pixel-major, quad-minor.
    // Output row byte c = (col*8 + c4)*16 + ... -> index (col*8 + c4).
    const unsigned oslot = col * 8u + c4;

    // prefetch flow for row 0
    float2 fln = __ldg(fl2 + (rowPix0 + col));

    #pragma unroll 1
    for (unsigned r = 0; r < TILE_H; ++r) {
        const unsigned y      = y0 + r;
        const unsigned rowPix = rowPix0 + r * W_;
        const unsigned st     = r & 1u;

        const float2 fl = fln;
        if (r + 1u < TILE_H)
            fln = __ldg(fl2 + (rowPix + W_ + col));  // next row's flow

        // bilinear gather (identical math to R10/reference)
        const float qy = (float)y - fl.x;
        const float qx = (float)x - fl.y;

        float fyf = floorf(qy);
        float fxf = floorf(qx);
        fyf = fminf(fmaxf(fyf, 0.0f), (float)(H_ - 2));
        fxf = fminf(fmaxf(fxf, 0.0f), (float)(W_ - 2));

        const float ay = fminf(fmaxf(qy - fyf, 0.0f), 1.0f);
        const float ax = fminf(fmaxf(qx - fxf, 0.0f), 1.0f);

        const unsigned rb =
            ((nH + (unsigned)(int)fyf) * W_ + (unsigned)(int)fxf) * C4_ + c4;

        const float4 tl = __ldg(img4 + rb);
        const float4 tr = __ldg(img4 + rb + C4_);
        const float4 bl = __ldg(img4 + rb + ROW4);
        const float4 br = __ldg(img4 + rb + ROW4 + C4_);

        const float4 res = bilerp4(tl, tr, bl, br, ax, ay);

        // ensure the bulk store that used buffer `st` (row r-2) finished
        // reading smem before we overwrite it
        if (tid == 0 && r >= 2u)
            asm volatile("cp.async.bulk.wait_group.read 1;" ::: "memory");
        __syncthreads();

        obuf[st][oslot] = res;                       // STS.128, conflict-free
        __syncthreads();

        if (tid == 0) {
            asm volatile("fence.proxy.async.shared::cta;" ::: "memory");
            const uint32_t saddr =
                (uint32_t)__cvta_generic_to_shared(&obuf[st][0]);
            const float* gdst = out + (size_t)rowPix * 32u;
            asm volatile(
                "cp.async.bulk.global.shared::cta.bulk_group [%0], [%1], %2;"
                :: "l"(gdst), "r"(saddr), "r"(ROW_BYTES) : "memory");
            asm volatile("cp.async.bulk.commit_group;" ::: "memory");
        }
    }

    // drain all bulk stores before the CTA can retire (smem reuse safety)
    if (tid == 0)
        asm volatile("cp.async.bulk.wait_group.read 0;" ::: "memory");
    __syncthreads();
}

extern "C" void kernel_launch(void* const* d_in, const int* in_sizes, int n_in,
                              void* d_out, int out_size)
{
    const float* image = (const float*)d_in[0];
    const float* flow  = (const float*)d_in[1];
    float* out = (float*)d_out;

    // N * TILES_PER_IMG = 8192 blocks, 256 threads each
    dense_warp_kernel<<<8192, 256>>>(image, flow, out);
}

// round 16
// speedup vs baseline: 1.2378x; 1.2378x over previous
#include <cuda_runtime.h>

// DenseWarpLayer: bilinear warp, N=8, H=512, W=512, C=32 fp32.
// FINAL = R10 (best measured: 92.2us wall / 92.3us kernel, DRAM 69.7%):
//  - persistent single-wave grid: 1184 blocks = 148 SMs x 8 resident blocks
//  - 8 threads/pixel: every warp-level LDG.128/STG.128 covers exactly
//    4 full 128B lines (C=32 floats = one line per bilinear corner)
//  - 2 sequential pixels per grid-stride task, both flow loads hoisted
//  - 32 registers -> 64 warps/SM (hard occupancy cliff found in R2/R3/R7)
//  - 1-iteration-ahead L1 prefetch of the next flow line (dedups in L1,
//    zero payload registers; +1% measured)
//
// Complete measured ledger (GB300 sm_103a):
//   register ILP / SW pipelines (R2,R3,R7)   -1..-18%  (occupancy cliff)
//   cp.async smem read staging (R8)          -13%      (regs + 2x L1 crossing)
//   32x8 tiling for L2->L1 reuse (R6)        flat      (hit latency not binding)
//   occupancy 83->95%, block shape (R9,R13)  flat
//   deeper L2 prefetch (R11)                 -37%      (redundant LTS traffic)
//   bulk TMA write bursting (R15)            -24%      (barrier serialization)
// All correct-pattern variants converge to ~93us kernel at ~5.5TB/s with
// DRAM traffic at the compulsory ~510MB floor: the achievable HBM efficiency
// (~69% of 8TB/s spec) for a fine-grained gather + stream-write mix.

#define N_ 8
#define H_ 512
#define W_ 512
#define C4_ 8u            // 32 channels = 8 float4
#define ROW4 (W_ * C4_)   // float4 per image row = 4096
#define NBLOCKS 1184u     // 148 SMs * 8 blocks -> exactly one wave
#define NTHREADS (NBLOCKS * 256u)
#define NTASKS 8388608u   // N*H*W*8 / 2 pixel-pair tasks
#define PIX_STRIDE 75776u // pixel offset between successive iterations
#define MAX_PIX 2097151u  // N*H*W - 1

__device__ __forceinline__ unsigned gather_base(unsigned pix, unsigned c4,
                                                const float2 fl,
                                                float& ax, float& ay)
{
    const unsigned w = pix & (W_ - 1);
    const unsigned h = (pix >> 9) & (H_ - 1);
    const unsigned n = pix >> 18;

    const float qy = (float)h - fl.x;
    const float qx = (float)w - fl.y;

    float fyf = floorf(qy);
    float fxf = floorf(qx);
    fyf = fminf(fmaxf(fyf, 0.0f), (float)(H_ - 2));
    fxf = fminf(fmaxf(fxf, 0.0f), (float)(W_ - 2));

    ay = fminf(fmaxf(qy - fyf, 0.0f), 1.0f);
    ax = fminf(fmaxf(qx - fxf, 0.0f), 1.0f);

    return ((n * H_ + (unsigned)(int)fyf) * W_ + (unsigned)(int)fxf) * C4_ + c4;
}

__device__ __forceinline__ float4 bilerp4(const float4 tl, const float4 tr,
                                          const float4 bl, const float4 br,
                                          const float ax, const float ay)
{
    float4 r; float top, bot;
    top = tl.x + ax * (tr.x - tl.x); bot = bl.x + ax * (br.x - bl.x);
    r.x = top + ay * (bot - top);
    top = tl.y + ax * (tr.y - tl.y); bot = bl.y + ax * (br.y - bl.y);
    r.y = top + ay * (bot - top);
    top = tl.z + ax * (tr.z - tl.z); bot = bl.z + ax * (br.z - bl.z);
    r.z = top + ay * (bot - top);
    top = tl.w + ax * (tr.w - tl.w); bot = bl.w + ax * (br.w - bl.w);
    r.w = top + ay * (bot - top);
    return r;
}

__device__ __forceinline__ void do_pixel(const float4* __restrict__ img4,
                                         float4* __restrict__ out4,
                                         unsigned pix, unsigned c4,
                                         const float2 fl)
{
    float ax, ay;
    const unsigned rb = gather_base(pix, c4, fl, ax, ay);

    const float4 tl = __ldg(img4 + rb);
    const float4 tr = __ldg(img4 + rb + C4_);
    const float4 bl = __ldg(img4 + rb + ROW4);
    const float4 br = __ldg(img4 + rb + ROW4 + C4_);

    out4[pix * C4_ + c4] = bilerp4(tl, tr, bl, br, ax, ay);
}

__global__ __launch_bounds__(256, 8)
void dense_warp_kernel(const float* __restrict__ image,
                       const float* __restrict__ flow,
                       float* __restrict__ out)
{
    const float2* fl2  = reinterpret_cast<const float2*>(flow);
    const float4* img4 = reinterpret_cast<const float4*>(image);
    float4*       out4 = reinterpret_cast<float4*>(out);

    const unsigned tid0 = blockIdx.x * 256u + threadIdx.x;

    #pragma unroll 1
    for (unsigned task = tid0; task < NTASKS; task += NTHREADS) {
        const unsigned c4   = task & 7u;
        const unsigned slot = task >> 3;
        const unsigned grp  = slot >> 2;
        const unsigned r    = slot & 3u;
        const unsigned pix0 = grp * 8u + r;
        const unsigned pix1 = pix0 + 4u;

        // prefetch NEXT iteration's flow line (covers both its pixels'
        // float2 values: +32B apart, always same 128B line). Clamped so the
        // final iteration prefetches a valid in-buffer address.
        {
            const unsigned npix = min(pix0 + PIX_STRIDE, MAX_PIX);
            asm volatile("prefetch.global.L1 [%0];" :: "l"(fl2 + npix));
        }

        // this iteration's flows (L1/L2 hits after warm-up)
        const float2 fl0 = __ldg(fl2 + pix0);
        const float2 fl1 = __ldg(fl2 + pix1);

        do_pixel(img4, out4, pix0, c4, fl0);
        do_pixel(img4, out4, pix1, c4, fl1);
    }
}

extern "C" void kernel_launch(void* const* d_in, const int* in_sizes, int n_in,
                              void* d_out, int out_size)
{
    const float* image = (const float*)d_in[0];
    const float* flow  = (const float*)d_in[1];
    float* out = (float*)d_out;

    dense_warp_kernel<<<NBLOCKS, 256>>>(image, flow, out);
}